// round 15
// baseline (speedup 1.0000x reference)
#include <cuda_runtime.h>
#include <cuda_fp16.h>
#include <cstdint>

#define BB 2
#define LL 2048
#define DM 1024
#define NH 16
#define MM (BB*LL)

// ---------------- device scratch (fp16) --------------------------------------
__device__ __align__(16) __half g_x16[MM*DM];                    // hi only
__device__ __align__(16) __half g_w16[4][DM*DM];                 // hi only
__device__ __align__(16) __half g_Qh16[MM*DM], g_Ql16[MM*DM];    // [bh][l][64], scaled log2e/8
__device__ __align__(16) __half g_K16[MM*DM];                    // [bh][l][64]
__device__ __align__(16) __half g_V16[MM*DM];                    // transposed [bh][d][l]
__device__ __align__(16) __half g_O16[MM*DM];                    // [b][l][1024] hi only

// ---------------- mma / ldmatrix / cp.async helpers -------------------------
__device__ __forceinline__ void mma16816(float* c, const uint32_t* a, const uint32_t* b){
    asm volatile("mma.sync.aligned.m16n8k16.row.col.f32.f16.f16.f32 "
        "{%0,%1,%2,%3}, {%4,%5,%6,%7}, {%8,%9}, {%0,%1,%2,%3};"
        : "+f"(c[0]), "+f"(c[1]), "+f"(c[2]), "+f"(c[3])
        : "r"(a[0]), "r"(a[1]), "r"(a[2]), "r"(a[3]), "r"(b[0]), "r"(b[1]));
}
__device__ __forceinline__ uint32_t smem_u32(const void* p){
    uint32_t a;
    asm("{ .reg .u64 t; cvta.to.shared.u64 t, %1; cvt.u32.u64 %0, t; }" : "=r"(a) : "l"(p));
    return a;
}
__device__ __forceinline__ void ldmA(uint32_t* a, const __half* s, int S, int m0, int k0, int lane){
    const __half* p = s + (size_t)(m0 + (lane & 15)) * S + k0 + ((lane >> 4) << 3);
    asm volatile("ldmatrix.sync.aligned.m8n8.x4.shared.b16 {%0,%1,%2,%3}, [%4];"
        : "=r"(a[0]), "=r"(a[1]), "=r"(a[2]), "=r"(a[3]) : "r"(smem_u32(p)));
}
__device__ __forceinline__ void ldmB(uint32_t* b, const __half* s, int S, int n0, int k0, int lane){
    const __half* p = s + (size_t)(n0 + (lane & 7)) * S + k0 + (((lane >> 3) & 1) << 3);
    asm volatile("ldmatrix.sync.aligned.m8n8.x2.shared.b16 {%0,%1}, [%2];"
        : "=r"(b[0]), "=r"(b[1]) : "r"(smem_u32(p)));
}
__device__ __forceinline__ void cp16(const __half* dst, const __half* src){
    asm volatile("cp.async.ca.shared.global [%0], [%1], 16;" :: "r"(smem_u32(dst)), "l"(src));
}
#define CP_COMMIT() asm volatile("cp.async.commit_group;" ::: "memory")
__device__ __forceinline__ void split_h(float v, __half& h, __half& l){
    h = __float2half_rn(v);
    l = __float2half_rn(v - __half2float(h));
}
__device__ __forceinline__ float fex2(float x){
    float y; asm("ex2.approx.f32 %0, %1;" : "=f"(y) : "f"(x)); return y;
}

// ============================================================================
// fp32 -> fp16 (hi only): x and 4 weights, one launch
// ============================================================================
__global__ __launch_bounds__(256) void cvt_all_kernel(
    const float* __restrict__ x,  const float* __restrict__ wq,
    const float* __restrict__ wk, const float* __restrict__ wv,
    const float* __restrict__ wo)
{
    size_t i4 = ((size_t)blockIdx.x * 256 + threadIdx.x) * 4;
    const float* s; __half* d; size_t off;
    if (i4 < (size_t)MM * DM) {
        s = x; d = g_x16; off = i4;
    } else {
        size_t j = i4 - (size_t)MM * DM;
        int t = (int)(j >> 20);
        off = j & ((1u << 20) - 1);
        s = (t == 0) ? wq : (t == 1) ? wk : (t == 2) ? wv : wo;
        d = g_w16[t];
    }
    float4 v = *(const float4*)(s + off);
    __half2 hh[2] = {__halves2half2(__float2half_rn(v.x), __float2half_rn(v.y)),
                     __halves2half2(__float2half_rn(v.z), __float2half_rn(v.w))};
    *(uint2*)(d + off) = *(uint2*)hh;
}

// ============================================================================
// projection GEMM: C = A @ B^T + bias (1-term fp16), cp.async 2-stage, K-step 64
// (exact R12 structure)
// ============================================================================
#define SA 72
#define STG (2*128*SA)     // 18432 halves per stage
__global__ __launch_bounds__(256, 2) void proj_kernel(
    const float* __restrict__ b0, const float* __restrict__ b1,
    const float* __restrict__ b2, float* __restrict__ fout, int mode_arg)
{
    extern __shared__ char smraw[];
    __half* S = (__half*)smraw;
    __shared__ float s_bias[128];

    const int mode = (mode_arg < 0) ? (int)blockIdx.z : mode_arg;
    const float* bias = (mode == 1) ? b1 : (mode == 2) ? b2 : b0;
    const __half* gA = (mode < 3) ? g_x16 : g_O16;
    const __half* gB = g_w16[mode];

    const int bm = blockIdx.y * 128, bn = blockIdx.x * 128;
    const int tid = threadIdx.x, w = tid >> 5, lane = tid & 31;
    const int wm = w >> 2, wn = w & 3;
    if (tid < 128) s_bias[tid] = bias[bn + tid];

    float C[4][4][4];
    #pragma unroll
    for (int i = 0; i < 4; i++)
        #pragma unroll
        for (int j = 0; j < 4; j++)
            #pragma unroll
            for (int q = 0; q < 4; q++) C[i][j][q] = 0.f;

    #pragma unroll
    for (int i = tid; i < 2048; i += 256) {
        int t = i >> 10, e = i & 1023, r = e >> 3, c8 = e & 7;
        const __half* src = t ? gB : gA;
        int rowbase = t ? bn : bm;
        cp16(S + t * 9216 + r * SA + c8 * 8, src + (size_t)(rowbase + r) * DM + c8 * 8);
    }
    CP_COMMIT();

    for (int it = 0; it < 16; it++) {
        const int cur = it & 1;
        if (it + 1 < 16) {
            const int k0n = (it + 1) * 64, nxt = cur ^ 1;
            #pragma unroll
            for (int i = tid; i < 2048; i += 256) {
                int t = i >> 10, e = i & 1023, r = e >> 3, c8 = e & 7;
                const __half* src = t ? gB : gA;
                int rowbase = t ? bn : bm;
                cp16(S + nxt * STG + t * 9216 + r * SA + c8 * 8,
                     src + (size_t)(rowbase + r) * DM + k0n + c8 * 8);
            }
            CP_COMMIT();
            asm volatile("cp.async.wait_group 1;" ::: "memory");
        } else {
            asm volatile("cp.async.wait_group 0;" ::: "memory");
        }
        __syncthreads();

        const __half *Ah = S + cur * STG, *Bh = Ah + 9216;
        #pragma unroll
        for (int ks = 0; ks < 4; ks++) {
            uint32_t fbh[4][2];
            #pragma unroll
            for (int nt = 0; nt < 4; nt++)
                ldmB(fbh[nt], Bh, SA, wn * 32 + nt * 8, ks * 16, lane);
            #pragma unroll
            for (int mt = 0; mt < 4; mt++) {
                uint32_t fah[4];
                ldmA(fah, Ah, SA, wm * 64 + mt * 16, ks * 16, lane);
                #pragma unroll
                for (int nt = 0; nt < 4; nt++)
                    mma16816(C[mt][nt], fah, fbh[nt]);
            }
        }
        __syncthreads();
    }

    const int r = lane >> 2, cq = lane & 3;
    const float scl = (mode == 0) ? 0.18033688011112042f : 1.0f;  // log2e/8
    #pragma unroll
    for (int mt = 0; mt < 4; mt++) {
        #pragma unroll
        for (int nt = 0; nt < 4; nt++) {
            int nloc = wn * 32 + nt * 8 + 2 * cq;
            int n = bn + nloc;
            #pragma unroll
            for (int hf = 0; hf < 2; hf++) {
                int m = bm + wm * 64 + mt * 16 + r + hf * 8;
                float v0 = (C[mt][nt][hf*2+0] + s_bias[nloc])     * scl;
                float v1 = (C[mt][nt][hf*2+1] + s_bias[nloc + 1]) * scl;
                if (mode == 3) {
                    *(float2*)(fout + (size_t)m * DM + n) = make_float2(v0, v1);
                } else {
                    int bidx = m >> 11, l = m & 2047, h = n >> 6, d = n & 63;
                    if (mode == 0) {
                        size_t idx = (((size_t)bidx * NH + h) * LL + l) * 64 + d;
                        __half h0,l0,h1,l1; split_h(v0,h0,l0); split_h(v1,h1,l1);
                        *(__half2*)(g_Qh16 + idx) = __halves2half2(h0, h1);
                        *(__half2*)(g_Ql16 + idx) = __halves2half2(l0, l1);
                    } else if (mode == 1) {
                        size_t idx = (((size_t)bidx * NH + h) * LL + l) * 64 + d;
                        *(__half2*)(g_K16 + idx) =
                            __halves2half2(__float2half_rn(v0), __float2half_rn(v1));
                    } else {
                        size_t idx = (((size_t)bidx * NH + h) * 64 + d) * LL + l;
                        g_V16[idx]      = __float2half_rn(v0);
                        g_V16[idx + LL] = __float2half_rn(v1);
                    }
                }
            }
        }
    }
}

// ============================================================================
// fused attention, TWO PASS, q-tile 128 as 2x64 subtiles sharing K/V loads.
// pass1: S = Qh.K (K double-buffered), both subs per K tile.
// pass2: K double-buffered, V single-buffered (loaded per kt, waited before
//        PV-sub0), P single buffer reused across subs. 5 syncs/kt.
// smem halves: Qh 0 (128 rows), Ql 9216, K0 18432, K1 27648, V 36864, P 45568
// total 54272 halves = 108544 B -> 2 CTAs/SM
// ============================================================================
#define SQ 72
#define SV 136
__global__ __launch_bounds__(256, 2) void attn_kernel(const int* __restrict__ mask,
                                                      float* __restrict__ attn){
    extern __shared__ char smraw[];
    __half* S = (__half*)smraw;
    __half *Qh = S,           *Ql = S + 9216,
           *K0 = S + 18432,   *K1 = S + 27648,
           *Vt = S + 36864,   *Pt = S + 45568;
    __shared__ float s_msk[128];
    __shared__ float s_rs[128][4];
    __shared__ float s_inv[128];

    const int bh = blockIdx.y, q0 = blockIdx.x * 128, b = bh >> 4;
    const int tid = threadIdx.x, w = tid >> 5, lane = tid & 31;
    const int wq = w >> 2, wn = w & 3;
    const int r = lane >> 2, cq = lane & 3;

    // persistent Q tile [128][64] hi/lo + prefetch pass-1 K stage 0
    #pragma unroll
    for (int i = tid; i < 2048; i += 256) {
        int t = i >> 10, e = i & 1023, rr = e >> 3, c8 = e & 7;
        const __half* src = (t ? g_Ql16 : g_Qh16) + ((size_t)bh * LL + q0) * 64;
        cp16((t ? Ql : Qh) + rr * SQ + c8 * 8, src + (size_t)rr * 64 + c8 * 8);
    }
    #pragma unroll
    for (int i = tid; i < 1024; i += 256) {
        int rr = i >> 3, c8 = i & 7;
        cp16(K0 + rr * SQ + c8 * 8,
             g_K16 + (size_t)bh * LL * 64 + (size_t)rr * 64 + c8 * 8);
    }
    CP_COMMIT();

    float rs[2][2][2];
    #pragma unroll
    for (int s2=0;s2<2;s2++) for (int i=0;i<2;i++) for (int j=0;j<2;j++) rs[s2][i][j]=0.f;

    // ---------------- pass 1: rowsums (Qh.K, both subs per K tile) ---------
    for (int kt = 0; kt < 16; kt++) {
        __syncthreads();
        const __half* Kcur = (kt & 1) ? K1 : K0;
        if (kt + 1 < 16) {
            __half* Knxt = (kt & 1) ? K0 : K1;
            const __half* src = g_K16 + ((size_t)bh * LL + (kt + 1) * 128) * 64;
            #pragma unroll
            for (int i = tid; i < 1024; i += 256) {
                int rr = i >> 3, c8 = i & 7;
                cp16(Knxt + rr * SQ + c8 * 8, src + (size_t)rr * 64 + c8 * 8);
            }
            CP_COMMIT();
            asm volatile("cp.async.wait_group 1;" ::: "memory");
        } else {
            asm volatile("cp.async.wait_group 0;" ::: "memory");
        }
        if (tid < 128) s_msk[tid] = mask[b * LL + kt * 128 + tid] ? 1.f : 0.f;
        __syncthreads();

        float Cs[2][2][4][4];   // [sub][mt][nt][q]
        #pragma unroll
        for (int s2=0;s2<2;s2++) for (int i=0;i<2;i++) for (int j=0;j<4;j++)
            #pragma unroll
            for (int q=0;q<4;q++) Cs[s2][i][j][q]=0.f;
        #pragma unroll
        for (int ks = 0; ks < 4; ks++) {
            uint32_t fbh[4][2];
            #pragma unroll
            for (int nt = 0; nt < 4; nt++)
                ldmB(fbh[nt], Kcur, SQ, wn * 32 + nt * 8, ks * 16, lane);
            #pragma unroll
            for (int sub = 0; sub < 2; sub++)
                #pragma unroll
                for (int mt = 0; mt < 2; mt++) {
                    uint32_t fah[4];
                    ldmA(fah, Qh, SQ, sub * 64 + wq * 32 + mt * 16, ks * 16, lane);
                    #pragma unroll
                    for (int nt = 0; nt < 4; nt++)
                        mma16816(Cs[sub][mt][nt], fah, fbh[nt]);
                }
        }
        #pragma unroll
        for (int sub = 0; sub < 2; sub++)
            #pragma unroll
            for (int mt = 0; mt < 2; mt++)
                #pragma unroll
                for (int nt = 0; nt < 4; nt++) {
                    int col = wn * 32 + nt * 8 + 2 * cq;
                    float m0 = s_msk[col], m1 = s_msk[col + 1];
                    #pragma unroll
                    for (int hf = 0; hf < 2; hf++)
                        rs[sub][mt][hf] += fex2(Cs[sub][mt][nt][hf*2+0]) * m0
                                         + fex2(Cs[sub][mt][nt][hf*2+1]) * m1;
                }
    }

    #pragma unroll
    for (int sub = 0; sub < 2; sub++)
        #pragma unroll
        for (int mt = 0; mt < 2; mt++)
            #pragma unroll
            for (int hf = 0; hf < 2; hf++) {
                rs[sub][mt][hf] += __shfl_xor_sync(0xffffffffu, rs[sub][mt][hf], 1);
                rs[sub][mt][hf] += __shfl_xor_sync(0xffffffffu, rs[sub][mt][hf], 2);
            }
    __syncthreads();
    if (cq == 0) {
        #pragma unroll
        for (int sub = 0; sub < 2; sub++)
            #pragma unroll
            for (int mt = 0; mt < 2; mt++)
                #pragma unroll
                for (int hf = 0; hf < 2; hf++)
                    s_rs[sub * 64 + wq * 32 + mt * 16 + r + hf * 8][wn] = rs[sub][mt][hf];
    }
    __syncthreads();
    if (tid < 128)
        s_inv[tid] = 1.f / (s_rs[tid][0] + s_rs[tid][1] + s_rs[tid][2] + s_rs[tid][3]);
    __syncthreads();

    float O[2][2][2][4];   // [sub][mt][nt][q]
    #pragma unroll
    for (int s2=0;s2<2;s2++) for (int i=0;i<2;i++) for (int j=0;j<2;j++)
        #pragma unroll
        for (int q=0;q<4;q++) O[s2][i][j][q]=0.f;
    float inv_r[2][2][2];
    #pragma unroll
    for (int sub = 0; sub < 2; sub++)
        #pragma unroll
        for (int mt = 0; mt < 2; mt++)
            #pragma unroll
            for (int hf = 0; hf < 2; hf++)
                inv_r[sub][mt][hf] = s_inv[sub * 64 + wq * 32 + mt * 16 + r + hf * 8];

    // prologue pass 2: K(0) into K0
    #pragma unroll
    for (int i = tid; i < 1024; i += 256) {
        int rr = i >> 3, c8 = i & 7;
        cp16(K0 + rr * SQ + c8 * 8,
             g_K16 + (size_t)bh * LL * 64 + (size_t)rr * 64 + c8 * 8);
    }
    CP_COMMIT();

    // ---------------- pass 2: normalized attn + O --------------------------
    for (int kt = 0; kt < 16; kt++) {
        const int k0g = kt * 128;
        const __half* Kc = (kt & 1) ? K1 : K0;
        __syncthreads();                     // sync_a: PV(kt-1) fully done
        // V(kt) into the single V buffer (group gV)
        {
            const __half* srcV = g_V16 + (size_t)bh * 64 * LL + k0g;
            #pragma unroll
            for (int i = tid; i < 1024; i += 256) {
                int rr = i >> 4, c8 = i & 15;
                cp16(Vt + rr * SV + c8 * 8, srcV + (size_t)rr * LL + c8 * 8);
            }
            CP_COMMIT();
        }
        if (kt + 1 < 16) {                   // K(kt+1) (group gK)
            __half* Kn = (kt & 1) ? K0 : K1;
            const __half* srcK = g_K16 + ((size_t)bh * LL + k0g + 128) * 64;
            #pragma unroll
            for (int i = tid; i < 1024; i += 256) {
                int rr = i >> 3, c8 = i & 7;
                cp16(Kn + rr * SQ + c8 * 8, srcK + (size_t)rr * 64 + c8 * 8);
            }
            CP_COMMIT();
            asm volatile("cp.async.wait_group 2;" ::: "memory");  // K(kt) done
        } else {
            asm volatile("cp.async.wait_group 1;" ::: "memory");  // K(kt) done
        }
        if (tid < 128) s_msk[tid] = mask[b * LL + k0g + tid] ? 1.f : 0.f;
        __syncthreads();                     // sync_b

        #pragma unroll
        for (int sub = 0; sub < 2; sub++) {
            // ---- S(sub) ----
            float Cs[2][4][4];
            #pragma unroll
            for (int i=0;i<2;i++) for (int j=0;j<4;j++)
                #pragma unroll
                for (int q=0;q<4;q++) Cs[i][j][q]=0.f;
            #pragma unroll
            for (int ks = 0; ks < 4; ks++) {
                uint32_t fbh[4][2];
                #pragma unroll
                for (int nt = 0; nt < 4; nt++)
                    ldmB(fbh[nt], Kc, SQ, wn * 32 + nt * 8, ks * 16, lane);
                #pragma unroll
                for (int mt = 0; mt < 2; mt++) {
                    uint32_t fah[4], fal[4];
                    ldmA(fah, Qh, SQ, sub * 64 + wq * 32 + mt * 16, ks * 16, lane);
                    ldmA(fal, Ql, SQ, sub * 64 + wq * 32 + mt * 16, ks * 16, lane);
                    #pragma unroll
                    for (int nt = 0; nt < 4; nt++) {
                        mma16816(Cs[mt][nt], fah, fbh[nt]);
                        mma16816(Cs[mt][nt], fal, fbh[nt]);
                    }
                }
            }
            if (sub == 1) __syncthreads();   // sync_d: PV(sub0) done reading Pt
            // ---- e, attn write, P(sub) ----
            #pragma unroll
            for (int mt = 0; mt < 2; mt++) {
                #pragma unroll
                for (int nt = 0; nt < 4; nt++) {
                    int col = wn * 32 + nt * 8 + 2 * cq;
                    float m0 = s_msk[col], m1 = s_msk[col + 1];
                    #pragma unroll
                    for (int hf = 0; hf < 2; hf++) {
                        int rloc = wq * 32 + mt * 16 + r + hf * 8;
                        float iv = inv_r[sub][mt][hf];
                        float e0 = fex2(Cs[mt][nt][hf*2+0]) * m0 * iv;
                        float e1 = fex2(Cs[mt][nt][hf*2+1]) * m1 * iv;
                        if (attn)
                            *(float2*)(attn + ((size_t)bh * LL + q0 + sub * 64 + rloc) * LL
                                       + k0g + col) = make_float2(e0, e1);
                        *(__half2*)(Pt + (size_t)rloc * SV + col) =
                            __halves2half2(__float2half_rn(e0), __float2half_rn(e1));
                    }
                }
            }
            if (sub == 0) {
                // V(kt) must be resident before PV-sub0 (gK(kt+1) may stay)
                if (kt + 1 < 16)
                    asm volatile("cp.async.wait_group 1;" ::: "memory");
                else
                    asm volatile("cp.async.wait_group 0;" ::: "memory");
            }
            __syncthreads();                 // sync_c / sync_e
            // ---- O(sub) += P.V ----
            #pragma unroll
            for (int ks = 0; ks < 8; ks++) {
                uint32_t vbh[2][2];
                #pragma unroll
                for (int nt = 0; nt < 2; nt++)
                    ldmB(vbh[nt], Vt, SV, wn * 16 + nt * 8, ks * 16, lane);
                #pragma unroll
                for (int mt = 0; mt < 2; mt++) {
                    uint32_t pah[4];
                    ldmA(pah, Pt, SV, wq * 32 + mt * 16, ks * 16, lane);
                    #pragma unroll
                    for (int nt = 0; nt < 2; nt++)
                        mma16816(O[sub][mt][nt], pah, vbh[nt]);
                }
            }
        }
    }

    // ---- O epilogue (already normalized; hi only) ----
    #pragma unroll
    for (int sub = 0; sub < 2; sub++)
        #pragma unroll
        for (int mt = 0; mt < 2; mt++)
            #pragma unroll
            for (int nt = 0; nt < 2; nt++) {
                int d = wn * 16 + nt * 8 + 2 * cq;
                #pragma unroll
                for (int hf = 0; hf < 2; hf++) {
                    int row = sub * 64 + wq * 32 + mt * 16 + r + hf * 8;
                    size_t idx = ((size_t)b * LL + q0 + row) * DM + (bh & 15) * 64 + d;
                    *(__half2*)(g_O16 + idx) =
                        __halves2half2(__float2half_rn(O[sub][mt][nt][hf*2+0]),
                                       __float2half_rn(O[sub][mt][nt][hf*2+1]));
                }
            }
}

// ============================================================================
extern "C" void kernel_launch(void* const* d_in, const int* in_sizes, int n_in,
                              void* d_out, int out_size)
{
    const float* x    = (const float*)d_in[0];
    const int*   mask = (const int*)  d_in[1];
    const float* bq   = (const float*)d_in[3];
    const float* bk   = (const float*)d_in[5];
    const float* bv   = (const float*)d_in[7];
    const float* bo   = (const float*)d_in[9];
    float* out = (float*)d_out;

    const size_t out_elems  = (size_t)MM * DM;
    const size_t attn_elems = (size_t)BB * NH * LL * LL;
    float* attn = ((size_t)out_size >= out_elems + attn_elems) ? (out + out_elems) : nullptr;

    const int smem_proj = 2 * STG * 2;     // 73728 B
    const int smem_attn = 108544;
    cudaFuncSetAttribute(proj_kernel, cudaFuncAttributeMaxDynamicSharedMemorySize, smem_proj);
    cudaFuncSetAttribute(attn_kernel, cudaFuncAttributeMaxDynamicSharedMemorySize, smem_attn);

    const size_t total_cvt = (size_t)MM * DM + 4 * (size_t)DM * DM;
    cvt_all_kernel<<<(int)(total_cvt / 4 / 256), 256>>>(
        x, (const float*)d_in[2], (const float*)d_in[4],
        (const float*)d_in[6], (const float*)d_in[8]);

    proj_kernel<<<dim3(8, 32, 3), 256, smem_proj>>>(bq, bk, bv, nullptr, -1);

    attn_kernel<<<dim3(LL / 128, BB * NH), 256, smem_attn>>>(mask, attn);

    proj_kernel<<<dim3(8, 32, 1), 256, smem_proj>>>(bo, nullptr, nullptr, out, 3);
}

// round 16
// speedup vs baseline: 1.0609x; 1.0609x over previous
#include <cuda_runtime.h>
#include <cuda_fp16.h>
#include <cstdint>

#define BB 2
#define LL 2048
#define DM 1024
#define NH 16
#define MM (BB*LL)

// ---------------- device scratch (fp16) --------------------------------------
__device__ __align__(16) __half g_x16[MM*DM];                    // hi only
__device__ __align__(16) __half g_w16[4][DM*DM];                 // hi only
__device__ __align__(16) __half g_Qh16[MM*DM], g_Ql16[MM*DM];    // [bh][l][64], scaled log2e/8
__device__ __align__(16) __half g_K16[MM*DM];                    // [bh][l][64]
__device__ __align__(16) __half g_V16[MM*DM];                    // transposed [bh][d][l]
__device__ __align__(16) __half g_O16[MM*DM];                    // [b][l][1024] hi only

// ---------------- mma / ldmatrix / cp.async helpers -------------------------
__device__ __forceinline__ void mma16816(float* c, const uint32_t* a, const uint32_t* b){
    asm volatile("mma.sync.aligned.m16n8k16.row.col.f32.f16.f16.f32 "
        "{%0,%1,%2,%3}, {%4,%5,%6,%7}, {%8,%9}, {%0,%1,%2,%3};"
        : "+f"(c[0]), "+f"(c[1]), "+f"(c[2]), "+f"(c[3])
        : "r"(a[0]), "r"(a[1]), "r"(a[2]), "r"(a[3]), "r"(b[0]), "r"(b[1]));
}
__device__ __forceinline__ uint32_t smem_u32(const void* p){
    uint32_t a;
    asm("{ .reg .u64 t; cvta.to.shared.u64 t, %1; cvt.u32.u64 %0, t; }" : "=r"(a) : "l"(p));
    return a;
}
__device__ __forceinline__ void ldmA(uint32_t* a, const __half* s, int S, int m0, int k0, int lane){
    const __half* p = s + (size_t)(m0 + (lane & 15)) * S + k0 + ((lane >> 4) << 3);
    asm volatile("ldmatrix.sync.aligned.m8n8.x4.shared.b16 {%0,%1,%2,%3}, [%4];"
        : "=r"(a[0]), "=r"(a[1]), "=r"(a[2]), "=r"(a[3]) : "r"(smem_u32(p)));
}
__device__ __forceinline__ void ldmB(uint32_t* b, const __half* s, int S, int n0, int k0, int lane){
    const __half* p = s + (size_t)(n0 + (lane & 7)) * S + k0 + (((lane >> 3) & 1) << 3);
    asm volatile("ldmatrix.sync.aligned.m8n8.x2.shared.b16 {%0,%1}, [%2];"
        : "=r"(b[0]), "=r"(b[1]) : "r"(smem_u32(p)));
}
__device__ __forceinline__ void cp16(const __half* dst, const __half* src){
    asm volatile("cp.async.ca.shared.global [%0], [%1], 16;" :: "r"(smem_u32(dst)), "l"(src));
}
#define CP_COMMIT() asm volatile("cp.async.commit_group;" ::: "memory")
__device__ __forceinline__ void split_h(float v, __half& h, __half& l){
    h = __float2half_rn(v);
    l = __float2half_rn(v - __half2float(h));
}
__device__ __forceinline__ float fex2(float x){
    float y; asm("ex2.approx.f32 %0, %1;" : "=f"(y) : "f"(x)); return y;
}

// ============================================================================
// fp32 -> fp16 (hi only): x and 4 weights, one launch, 8 elems/thread
// ============================================================================
__global__ __launch_bounds__(256) void cvt_all_kernel(
    const float* __restrict__ x,  const float* __restrict__ wq,
    const float* __restrict__ wk, const float* __restrict__ wv,
    const float* __restrict__ wo)
{
    size_t base = ((size_t)blockIdx.x * 256 + threadIdx.x) * 8;
    #pragma unroll
    for (int half8 = 0; half8 < 2; half8++) {
        size_t i4 = base + half8 * 4;
        const float* s; __half* d; size_t off;
        if (i4 < (size_t)MM * DM) {
            s = x; d = g_x16; off = i4;
        } else {
            size_t j = i4 - (size_t)MM * DM;
            int t = (int)(j >> 20);
            off = j & ((1u << 20) - 1);
            s = (t == 0) ? wq : (t == 1) ? wk : (t == 2) ? wv : wo;
            d = g_w16[t];
        }
        float4 v = *(const float4*)(s + off);
        __half2 hh[2] = {__halves2half2(__float2half_rn(v.x), __float2half_rn(v.y)),
                         __halves2half2(__float2half_rn(v.z), __float2half_rn(v.w))};
        *(uint2*)(d + off) = *(uint2*)hh;
    }
}

// ============================================================================
// projection GEMM: C = A @ B^T + bias (1-term fp16), cp.async 2-stage, K-step 64
// (exact R12 structure)
// ============================================================================
#define SA 72
#define STG (2*128*SA)     // 18432 halves per stage
__global__ __launch_bounds__(256, 2) void proj_kernel(
    const float* __restrict__ b0, const float* __restrict__ b1,
    const float* __restrict__ b2, float* __restrict__ fout, int mode_arg)
{
    extern __shared__ char smraw[];
    __half* S = (__half*)smraw;
    __shared__ float s_bias[128];

    const int mode = (mode_arg < 0) ? (int)blockIdx.z : mode_arg;
    const float* bias = (mode == 1) ? b1 : (mode == 2) ? b2 : b0;
    const __half* gA = (mode < 3) ? g_x16 : g_O16;
    const __half* gB = g_w16[mode];

    const int bm = blockIdx.y * 128, bn = blockIdx.x * 128;
    const int tid = threadIdx.x, w = tid >> 5, lane = tid & 31;
    const int wm = w >> 2, wn = w & 3;
    if (tid < 128) s_bias[tid] = bias[bn + tid];

    float C[4][4][4];
    #pragma unroll
    for (int i = 0; i < 4; i++)
        #pragma unroll
        for (int j = 0; j < 4; j++)
            #pragma unroll
            for (int q = 0; q < 4; q++) C[i][j][q] = 0.f;

    #pragma unroll
    for (int i = tid; i < 2048; i += 256) {
        int t = i >> 10, e = i & 1023, r = e >> 3, c8 = e & 7;
        const __half* src = t ? gB : gA;
        int rowbase = t ? bn : bm;
        cp16(S + t * 9216 + r * SA + c8 * 8, src + (size_t)(rowbase + r) * DM + c8 * 8);
    }
    CP_COMMIT();

    for (int it = 0; it < 16; it++) {
        const int cur = it & 1;
        if (it + 1 < 16) {
            const int k0n = (it + 1) * 64, nxt = cur ^ 1;
            #pragma unroll
            for (int i = tid; i < 2048; i += 256) {
                int t = i >> 10, e = i & 1023, r = e >> 3, c8 = e & 7;
                const __half* src = t ? gB : gA;
                int rowbase = t ? bn : bm;
                cp16(S + nxt * STG + t * 9216 + r * SA + c8 * 8,
                     src + (size_t)(rowbase + r) * DM + k0n + c8 * 8);
            }
            CP_COMMIT();
            asm volatile("cp.async.wait_group 1;" ::: "memory");
        } else {
            asm volatile("cp.async.wait_group 0;" ::: "memory");
        }
        __syncthreads();

        const __half *Ah = S + cur * STG, *Bh = Ah + 9216;
        #pragma unroll
        for (int ks = 0; ks < 4; ks++) {
            uint32_t fbh[4][2];
            #pragma unroll
            for (int nt = 0; nt < 4; nt++)
                ldmB(fbh[nt], Bh, SA, wn * 32 + nt * 8, ks * 16, lane);
            #pragma unroll
            for (int mt = 0; mt < 4; mt++) {
                uint32_t fah[4];
                ldmA(fah, Ah, SA, wm * 64 + mt * 16, ks * 16, lane);
                #pragma unroll
                for (int nt = 0; nt < 4; nt++)
                    mma16816(C[mt][nt], fah, fbh[nt]);
            }
        }
        __syncthreads();
    }

    const int r = lane >> 2, cq = lane & 3;
    const float scl = (mode == 0) ? 0.18033688011112042f : 1.0f;  // log2e/8
    #pragma unroll
    for (int mt = 0; mt < 4; mt++) {
        #pragma unroll
        for (int nt = 0; nt < 4; nt++) {
            int nloc = wn * 32 + nt * 8 + 2 * cq;
            int n = bn + nloc;
            #pragma unroll
            for (int hf = 0; hf < 2; hf++) {
                int m = bm + wm * 64 + mt * 16 + r + hf * 8;
                float v0 = (C[mt][nt][hf*2+0] + s_bias[nloc])     * scl;
                float v1 = (C[mt][nt][hf*2+1] + s_bias[nloc + 1]) * scl;
                if (mode == 3) {
                    *(float2*)(fout + (size_t)m * DM + n) = make_float2(v0, v1);
                } else {
                    int bidx = m >> 11, l = m & 2047, h = n >> 6, d = n & 63;
                    if (mode == 0) {
                        size_t idx = (((size_t)bidx * NH + h) * LL + l) * 64 + d;
                        __half h0,l0,h1,l1; split_h(v0,h0,l0); split_h(v1,h1,l1);
                        *(__half2*)(g_Qh16 + idx) = __halves2half2(h0, h1);
                        *(__half2*)(g_Ql16 + idx) = __halves2half2(l0, l1);
                    } else if (mode == 1) {
                        size_t idx = (((size_t)bidx * NH + h) * LL + l) * 64 + d;
                        *(__half2*)(g_K16 + idx) =
                            __halves2half2(__float2half_rn(v0), __float2half_rn(v1));
                    } else {
                        size_t idx = (((size_t)bidx * NH + h) * 64 + d) * LL + l;
                        g_V16[idx]      = __float2half_rn(v0);
                        g_V16[idx + LL] = __float2half_rn(v1);
                    }
                }
            }
        }
    }
}

// ============================================================================
// fused attention, TWO PASS, q-tile 64, fp16 (R12 base).
// pass1: S = Qh.K (K double-buffered), Q A-fragments HOISTED (kt-invariant).
// pass2: exact R12: K/V double-buffered, separate P buffer, 2 syncs/kt.
// smem halves: Qh 0, Ql 4608, K0 9216, K1 18432, V0 27648, V1 36352, P 45056
// ============================================================================
#define SQ 72
#define SV 136
__global__ __launch_bounds__(256, 2) void attn_kernel(const int* __restrict__ mask,
                                                      float* __restrict__ attn){
    extern __shared__ char smraw[];
    __half* S = (__half*)smraw;
    __half *Qh = S,          *Ql = S + 4608,
           *K0 = S + 9216,   *K1 = S + 18432,
           *V0 = S + 27648,  *V1 = S + 36352,
           *Pt = S + 45056;
    __shared__ float s_msk[128];
    __shared__ float s_rs[64][4];
    __shared__ float s_inv[64];

    const int bh = blockIdx.y, q0 = blockIdx.x * 64, b = bh >> 4;
    const int tid = threadIdx.x, w = tid >> 5, lane = tid & 31;
    const int wq = w >> 2, wn = w & 3;
    const int r = lane >> 2, cq = lane & 3;

    // persistent Q tile [64][64] hi/lo + prefetch pass-1 K stage 0
    #pragma unroll
    for (int i = tid; i < 1024; i += 256) {
        int t = i >> 9, e = i & 511, rr = e >> 3, c8 = e & 7;
        const __half* src = (t ? g_Ql16 : g_Qh16) + ((size_t)bh * LL + q0) * 64;
        cp16((t ? Ql : Qh) + rr * SQ + c8 * 8, src + (size_t)rr * 64 + c8 * 8);
    }
    #pragma unroll
    for (int i = tid; i < 1024; i += 256) {
        int rr = i >> 3, c8 = i & 7;
        cp16(K0 + rr * SQ + c8 * 8,
             g_K16 + (size_t)bh * LL * 64 + (size_t)rr * 64 + c8 * 8);
    }
    CP_COMMIT();

    float rs[2][2] = {{0,0},{0,0}};
    uint32_t qa[4][2][4];          // hoisted Qh fragments [ks][mt]
    bool qloaded = false;

    // ---------------- pass 1: rowsums (Qh.K, double-buffered) --------------
    for (int kt = 0; kt < 16; kt++) {
        __syncthreads();
        const __half* Kcur = (kt & 1) ? K1 : K0;
        if (kt + 1 < 16) {
            __half* Knxt = (kt & 1) ? K0 : K1;
            const __half* src = g_K16 + ((size_t)bh * LL + (kt + 1) * 128) * 64;
            #pragma unroll
            for (int i = tid; i < 1024; i += 256) {
                int rr = i >> 3, c8 = i & 7;
                cp16(Knxt + rr * SQ + c8 * 8, src + (size_t)rr * 64 + c8 * 8);
            }
            CP_COMMIT();
            asm volatile("cp.async.wait_group 1;" ::: "memory");
        } else {
            asm volatile("cp.async.wait_group 0;" ::: "memory");
        }
        if (tid < 128) s_msk[tid] = mask[b * LL + kt * 128 + tid] ? 1.f : 0.f;
        __syncthreads();

        if (!qloaded) {     // Q tile resident (same cp group as K stage 0)
            #pragma unroll
            for (int ks = 0; ks < 4; ks++)
                #pragma unroll
                for (int mt = 0; mt < 2; mt++)
                    ldmA(qa[ks][mt], Qh, SQ, wq * 32 + mt * 16, ks * 16, lane);
            qloaded = true;
        }

        float Cs[2][4][4];
        #pragma unroll
        for (int i=0;i<2;i++) for (int j=0;j<4;j++) for (int q=0;q<4;q++) Cs[i][j][q]=0.f;
        #pragma unroll
        for (int ks = 0; ks < 4; ks++) {
            uint32_t fbh[4][2];
            #pragma unroll
            for (int nt = 0; nt < 4; nt++)
                ldmB(fbh[nt], Kcur, SQ, wn * 32 + nt * 8, ks * 16, lane);
            #pragma unroll
            for (int mt = 0; mt < 2; mt++)
                #pragma unroll
                for (int nt = 0; nt < 4; nt++)
                    mma16816(Cs[mt][nt], qa[ks][mt], fbh[nt]);
        }
        #pragma unroll
        for (int mt = 0; mt < 2; mt++)
            #pragma unroll
            for (int nt = 0; nt < 4; nt++) {
                int col = wn * 32 + nt * 8 + 2 * cq;
                float m0 = s_msk[col], m1 = s_msk[col + 1];
                #pragma unroll
                for (int hf = 0; hf < 2; hf++)
                    rs[mt][hf] += fex2(Cs[mt][nt][hf*2+0]) * m0
                                + fex2(Cs[mt][nt][hf*2+1]) * m1;
            }
    }

    #pragma unroll
    for (int mt = 0; mt < 2; mt++)
        #pragma unroll
        for (int hf = 0; hf < 2; hf++) {
            rs[mt][hf] += __shfl_xor_sync(0xffffffffu, rs[mt][hf], 1);
            rs[mt][hf] += __shfl_xor_sync(0xffffffffu, rs[mt][hf], 2);
        }
    __syncthreads();
    if (cq == 0) {
        #pragma unroll
        for (int mt = 0; mt < 2; mt++)
            #pragma unroll
            for (int hf = 0; hf < 2; hf++)
                s_rs[wq * 32 + mt * 16 + r + hf * 8][wn] = rs[mt][hf];
    }
    __syncthreads();
    if (tid < 64)
        s_inv[tid] = 1.f / (s_rs[tid][0] + s_rs[tid][1] + s_rs[tid][2] + s_rs[tid][3]);
    __syncthreads();

    float O[2][2][4];
    #pragma unroll
    for (int i=0;i<2;i++) for (int j=0;j<2;j++) for (int q=0;q<4;q++) O[i][j][q]=0.f;
    float inv_r[2][2];
    #pragma unroll
    for (int mt = 0; mt < 2; mt++)
        #pragma unroll
        for (int hf = 0; hf < 2; hf++)
            inv_r[mt][hf] = s_inv[wq * 32 + mt * 16 + r + hf * 8];

    // prologue pass 2: load kt=0 K,V into buffer 0
    {
        const __half* srcK = g_K16 + (size_t)bh * LL * 64;
        const __half* srcV = g_V16 + (size_t)bh * 64 * LL;
        #pragma unroll
        for (int i = tid; i < 1024; i += 256) {
            int rr = i >> 3, c8 = i & 7;
            cp16(K0 + rr * SQ + c8 * 8, srcK + (size_t)rr * 64 + c8 * 8);
        }
        #pragma unroll
        for (int i = tid; i < 1024; i += 256) {
            int rr = i >> 4, c8 = i & 15;
            cp16(V0 + rr * SV + c8 * 8, srcV + (size_t)rr * LL + c8 * 8);
        }
        CP_COMMIT();
    }

    // ---------------- pass 2: normalized attn + O (K/V double-buffered) ----
    for (int kt = 0; kt < 16; kt++) {
        const int k0g = kt * 128;
        const __half *Kc = (kt & 1) ? K1 : K0;
        const __half *Vc = (kt & 1) ? V1 : V0;
        __syncthreads();                       // PV(kt-1) done everywhere
        if (kt + 1 < 16) {
            __half* Kn = (kt & 1) ? K0 : K1;
            __half* Vn = (kt & 1) ? V0 : V1;
            const __half* srcK = g_K16 + ((size_t)bh * LL + k0g + 128) * 64;
            const __half* srcV = g_V16 + (size_t)bh * 64 * LL + k0g + 128;
            #pragma unroll
            for (int i = tid; i < 1024; i += 256) {
                int rr = i >> 3, c8 = i & 7;
                cp16(Kn + rr * SQ + c8 * 8, srcK + (size_t)rr * 64 + c8 * 8);
            }
            #pragma unroll
            for (int i = tid; i < 1024; i += 256) {
                int rr = i >> 4, c8 = i & 15;
                cp16(Vn + rr * SV + c8 * 8, srcV + (size_t)rr * LL + c8 * 8);
            }
            CP_COMMIT();
            asm volatile("cp.async.wait_group 1;" ::: "memory");
        } else {
            asm volatile("cp.async.wait_group 0;" ::: "memory");
        }
        if (tid < 128) s_msk[tid] = mask[b * LL + k0g + tid] ? 1.f : 0.f;
        __syncthreads();

        float Cs[2][4][4];
        #pragma unroll
        for (int i=0;i<2;i++) for (int j=0;j<4;j++) for (int q=0;q<4;q++) Cs[i][j][q]=0.f;
        #pragma unroll
        for (int ks = 0; ks < 4; ks++) {
            uint32_t fbh[4][2];
            #pragma unroll
            for (int nt = 0; nt < 4; nt++)
                ldmB(fbh[nt], Kc, SQ, wn * 32 + nt * 8, ks * 16, lane);
            #pragma unroll
            for (int mt = 0; mt < 2; mt++) {
                uint32_t fal[4];
                ldmA(fal, Ql, SQ, wq * 32 + mt * 16, ks * 16, lane);
                #pragma unroll
                for (int nt = 0; nt < 4; nt++) {
                    mma16816(Cs[mt][nt], qa[ks][mt], fbh[nt]);
                    mma16816(Cs[mt][nt], fal, fbh[nt]);
                }
            }
        }

        #pragma unroll
        for (int mt = 0; mt < 2; mt++) {
            #pragma unroll
            for (int nt = 0; nt < 4; nt++) {
                int col = wn * 32 + nt * 8 + 2 * cq;
                float m0 = s_msk[col], m1 = s_msk[col + 1];
                #pragma unroll
                for (int hf = 0; hf < 2; hf++) {
                    int row = wq * 32 + mt * 16 + r + hf * 8;
                    float iv = inv_r[mt][hf];
                    float e0 = fex2(Cs[mt][nt][hf*2+0]) * m0 * iv;
                    float e1 = fex2(Cs[mt][nt][hf*2+1]) * m1 * iv;
                    if (attn)
                        *(float2*)(attn + ((size_t)bh * LL + q0 + row) * LL + k0g + col) =
                            make_float2(e0, e1);
                    *(__half2*)(Pt + (size_t)row * SV + col) =
                        __halves2half2(__float2half_rn(e0), __float2half_rn(e1));
                }
            }
        }
        __syncthreads();

        #pragma unroll
        for (int ks = 0; ks < 8; ks++) {
            uint32_t vbh[2][2];
            #pragma unroll
            for (int nt = 0; nt < 2; nt++)
                ldmB(vbh[nt], Vc, SV, wn * 16 + nt * 8, ks * 16, lane);
            #pragma unroll
            for (int mt = 0; mt < 2; mt++) {
                uint32_t pah[4];
                ldmA(pah, Pt, SV, wq * 32 + mt * 16, ks * 16, lane);
                #pragma unroll
                for (int nt = 0; nt < 2; nt++)
                    mma16816(O[mt][nt], pah, vbh[nt]);
            }
        }
    }

    // ---- O epilogue (already normalized; hi only) ----
    #pragma unroll
    for (int mt = 0; mt < 2; mt++) {
        #pragma unroll
        for (int nt = 0; nt < 2; nt++) {
            int d = wn * 16 + nt * 8 + 2 * cq;
            #pragma unroll
            for (int hf = 0; hf < 2; hf++) {
                int row = wq * 32 + mt * 16 + r + hf * 8;
                size_t idx = ((size_t)b * LL + q0 + row) * DM + (bh & 15) * 64 + d;
                *(__half2*)(g_O16 + idx) =
                    __halves2half2(__float2half_rn(O[mt][nt][hf*2+0]),
                                   __float2half_rn(O[mt][nt][hf*2+1]));
            }
        }
    }
}

// ============================================================================
extern "C" void kernel_launch(void* const* d_in, const int* in_sizes, int n_in,
                              void* d_out, int out_size)
{
    const float* x    = (const float*)d_in[0];
    const int*   mask = (const int*)  d_in[1];
    const float* bq   = (const float*)d_in[3];
    const float* bk   = (const float*)d_in[5];
    const float* bv   = (const float*)d_in[7];
    const float* bo   = (const float*)d_in[9];
    float* out = (float*)d_out;

    const size_t out_elems  = (size_t)MM * DM;
    const size_t attn_elems = (size_t)BB * NH * LL * LL;
    float* attn = ((size_t)out_size >= out_elems + attn_elems) ? (out + out_elems) : nullptr;

    const int smem_proj = 2 * STG * 2;     // 73728 B
    const int smem_attn = 107520;
    cudaFuncSetAttribute(proj_kernel, cudaFuncAttributeMaxDynamicSharedMemorySize, smem_proj);
    cudaFuncSetAttribute(attn_kernel, cudaFuncAttributeMaxDynamicSharedMemorySize, smem_attn);

    const size_t total_cvt = (size_t)MM * DM + 4 * (size_t)DM * DM;
    cvt_all_kernel<<<(int)(total_cvt / 8 / 256), 256>>>(
        x, (const float*)d_in[2], (const float*)d_in[4],
        (const float*)d_in[6], (const float*)d_in[8]);

    proj_kernel<<<dim3(8, 32, 3), 256, smem_proj>>>(bq, bk, bv, nullptr, -1);

    attn_kernel<<<dim3(LL / 64, BB * NH), 256, smem_attn>>>(mask, attn);

    proj_kernel<<<dim3(8, 32, 1), 256, smem_proj>>>(bo, nullptr, nullptr, out, 3);
}

// round 17
// speedup vs baseline: 1.0873x; 1.0249x over previous
#include <cuda_runtime.h>
#include <cuda_fp16.h>
#include <cstdint>

#define BB 2
#define LL 2048
#define DM 1024
#define NH 16
#define MM (BB*LL)

// ---------------- device scratch (fp16) --------------------------------------
__device__ __align__(16) __half g_x16[MM*DM];                    // hi only
__device__ __align__(16) __half g_w16[4][DM*DM];                 // hi only
__device__ __align__(16) __half g_Qh16[MM*DM], g_Ql16[MM*DM];    // [bh][l][64], scaled log2e/8
__device__ __align__(16) __half g_K16[MM*DM];                    // [bh][l][64]
__device__ __align__(16) __half g_V16[MM*DM];                    // transposed [bh][d][l]
__device__ __align__(16) __half g_O16[MM*DM];                    // [b][l][1024] hi only

// ---------------- mma / ldmatrix / cp.async helpers -------------------------
__device__ __forceinline__ void mma16816(float* c, const uint32_t* a, const uint32_t* b){
    asm volatile("mma.sync.aligned.m16n8k16.row.col.f32.f16.f16.f32 "
        "{%0,%1,%2,%3}, {%4,%5,%6,%7}, {%8,%9}, {%0,%1,%2,%3};"
        : "+f"(c[0]), "+f"(c[1]), "+f"(c[2]), "+f"(c[3])
        : "r"(a[0]), "r"(a[1]), "r"(a[2]), "r"(a[3]), "r"(b[0]), "r"(b[1]));
}
__device__ __forceinline__ uint32_t smem_u32(const void* p){
    uint32_t a;
    asm("{ .reg .u64 t; cvta.to.shared.u64 t, %1; cvt.u32.u64 %0, t; }" : "=r"(a) : "l"(p));
    return a;
}
__device__ __forceinline__ void ldmA(uint32_t* a, const __half* s, int S, int m0, int k0, int lane){
    const __half* p = s + (size_t)(m0 + (lane & 15)) * S + k0 + ((lane >> 4) << 3);
    asm volatile("ldmatrix.sync.aligned.m8n8.x4.shared.b16 {%0,%1,%2,%3}, [%4];"
        : "=r"(a[0]), "=r"(a[1]), "=r"(a[2]), "=r"(a[3]) : "r"(smem_u32(p)));
}
__device__ __forceinline__ void ldmB(uint32_t* b, const __half* s, int S, int n0, int k0, int lane){
    const __half* p = s + (size_t)(n0 + (lane & 7)) * S + k0 + (((lane >> 3) & 1) << 3);
    asm volatile("ldmatrix.sync.aligned.m8n8.x2.shared.b16 {%0,%1}, [%2];"
        : "=r"(b[0]), "=r"(b[1]) : "r"(smem_u32(p)));
}
__device__ __forceinline__ void cp16(const __half* dst, const __half* src){
    asm volatile("cp.async.ca.shared.global [%0], [%1], 16;" :: "r"(smem_u32(dst)), "l"(src));
}
#define CP_COMMIT() asm volatile("cp.async.commit_group;" ::: "memory")
__device__ __forceinline__ void split_h(float v, __half& h, __half& l){
    h = __float2half_rn(v);
    l = __float2half_rn(v - __half2float(h));
}
__device__ __forceinline__ float fex2(float x){
    float y; asm("ex2.approx.f32 %0, %1;" : "=f"(y) : "f"(x)); return y;
}

// ============================================================================
// fp32 -> fp16 (hi only): x and 4 weights, one launch, 8 elems/thread
// ============================================================================
__global__ __launch_bounds__(256) void cvt_all_kernel(
    const float* __restrict__ x,  const float* __restrict__ wq,
    const float* __restrict__ wk, const float* __restrict__ wv,
    const float* __restrict__ wo)
{
    size_t base = ((size_t)blockIdx.x * 256 + threadIdx.x) * 8;
    #pragma unroll
    for (int half8 = 0; half8 < 2; half8++) {
        size_t i4 = base + half8 * 4;
        const float* s; __half* d; size_t off;
        if (i4 < (size_t)MM * DM) {
            s = x; d = g_x16; off = i4;
        } else {
            size_t j = i4 - (size_t)MM * DM;
            int t = (int)(j >> 20);
            off = j & ((1u << 20) - 1);
            s = (t == 0) ? wq : (t == 1) ? wk : (t == 2) ? wv : wo;
            d = g_w16[t];
        }
        float4 v = *(const float4*)(s + off);
        __half2 hh[2] = {__halves2half2(__float2half_rn(v.x), __float2half_rn(v.y)),
                         __halves2half2(__float2half_rn(v.z), __float2half_rn(v.w))};
        *(uint2*)(d + off) = *(uint2*)hh;
    }
}

// ============================================================================
// projection GEMM: C = A @ B^T + bias (1-term fp16), cp.async 2-stage, K-step 64
// (exact R12 structure)
// ============================================================================
#define SA 72
#define STG (2*128*SA)     // 18432 halves per stage
__global__ __launch_bounds__(256, 2) void proj_kernel(
    const float* __restrict__ b0, const float* __restrict__ b1,
    const float* __restrict__ b2, float* __restrict__ fout, int mode_arg)
{
    extern __shared__ char smraw[];
    __half* S = (__half*)smraw;
    __shared__ float s_bias[128];

    const int mode = (mode_arg < 0) ? (int)blockIdx.z : mode_arg;
    const float* bias = (mode == 1) ? b1 : (mode == 2) ? b2 : b0;
    const __half* gA = (mode < 3) ? g_x16 : g_O16;
    const __half* gB = g_w16[mode];

    const int bm = blockIdx.y * 128, bn = blockIdx.x * 128;
    const int tid = threadIdx.x, w = tid >> 5, lane = tid & 31;
    const int wm = w >> 2, wn = w & 3;
    if (tid < 128) s_bias[tid] = bias[bn + tid];

    float C[4][4][4];
    #pragma unroll
    for (int i = 0; i < 4; i++)
        #pragma unroll
        for (int j = 0; j < 4; j++)
            #pragma unroll
            for (int q = 0; q < 4; q++) C[i][j][q] = 0.f;

    #pragma unroll
    for (int i = tid; i < 2048; i += 256) {
        int t = i >> 10, e = i & 1023, r = e >> 3, c8 = e & 7;
        const __half* src = t ? gB : gA;
        int rowbase = t ? bn : bm;
        cp16(S + t * 9216 + r * SA + c8 * 8, src + (size_t)(rowbase + r) * DM + c8 * 8);
    }
    CP_COMMIT();

    for (int it = 0; it < 16; it++) {
        const int cur = it & 1;
        if (it + 1 < 16) {
            const int k0n = (it + 1) * 64, nxt = cur ^ 1;
            #pragma unroll
            for (int i = tid; i < 2048; i += 256) {
                int t = i >> 10, e = i & 1023, r = e >> 3, c8 = e & 7;
                const __half* src = t ? gB : gA;
                int rowbase = t ? bn : bm;
                cp16(S + nxt * STG + t * 9216 + r * SA + c8 * 8,
                     src + (size_t)(rowbase + r) * DM + k0n + c8 * 8);
            }
            CP_COMMIT();
            asm volatile("cp.async.wait_group 1;" ::: "memory");
        } else {
            asm volatile("cp.async.wait_group 0;" ::: "memory");
        }
        __syncthreads();

        const __half *Ah = S + cur * STG, *Bh = Ah + 9216;
        #pragma unroll
        for (int ks = 0; ks < 4; ks++) {
            uint32_t fbh[4][2];
            #pragma unroll
            for (int nt = 0; nt < 4; nt++)
                ldmB(fbh[nt], Bh, SA, wn * 32 + nt * 8, ks * 16, lane);
            #pragma unroll
            for (int mt = 0; mt < 4; mt++) {
                uint32_t fah[4];
                ldmA(fah, Ah, SA, wm * 64 + mt * 16, ks * 16, lane);
                #pragma unroll
                for (int nt = 0; nt < 4; nt++)
                    mma16816(C[mt][nt], fah, fbh[nt]);
            }
        }
        __syncthreads();
    }

    const int r = lane >> 2, cq = lane & 3;
    const float scl = (mode == 0) ? 0.18033688011112042f : 1.0f;  // log2e/8
    #pragma unroll
    for (int mt = 0; mt < 4; mt++) {
        #pragma unroll
        for (int nt = 0; nt < 4; nt++) {
            int nloc = wn * 32 + nt * 8 + 2 * cq;
            int n = bn + nloc;
            #pragma unroll
            for (int hf = 0; hf < 2; hf++) {
                int m = bm + wm * 64 + mt * 16 + r + hf * 8;
                float v0 = (C[mt][nt][hf*2+0] + s_bias[nloc])     * scl;
                float v1 = (C[mt][nt][hf*2+1] + s_bias[nloc + 1]) * scl;
                if (mode == 3) {
                    *(float2*)(fout + (size_t)m * DM + n) = make_float2(v0, v1);
                } else {
                    int bidx = m >> 11, l = m & 2047, h = n >> 6, d = n & 63;
                    if (mode == 0) {
                        size_t idx = (((size_t)bidx * NH + h) * LL + l) * 64 + d;
                        __half h0,l0,h1,l1; split_h(v0,h0,l0); split_h(v1,h1,l1);
                        *(__half2*)(g_Qh16 + idx) = __halves2half2(h0, h1);
                        *(__half2*)(g_Ql16 + idx) = __halves2half2(l0, l1);
                    } else if (mode == 1) {
                        size_t idx = (((size_t)bidx * NH + h) * LL + l) * 64 + d;
                        *(__half2*)(g_K16 + idx) =
                            __halves2half2(__float2half_rn(v0), __float2half_rn(v1));
                    } else {
                        size_t idx = (((size_t)bidx * NH + h) * 64 + d) * LL + l;
                        g_V16[idx]      = __float2half_rn(v0);
                        g_V16[idx + LL] = __float2half_rn(v1);
                    }
                }
            }
        }
    }
}

// ============================================================================
// fused attention, TWO PASS, q-tile 64, fp16 (EXACT R12 structure).
// pass1: S = Qh.K (K double-buffered), rowsums -> inv.
// pass2: K AND V double-buffered, separate P buffer.
// smem halves: Qh 0, Ql 4608, K0 9216, K1 18432, V0 27648, V1 36352, P 45056
// ============================================================================
#define SQ 72
#define SV 136
__global__ __launch_bounds__(256, 2) void attn_kernel(const int* __restrict__ mask,
                                                      float* __restrict__ attn){
    extern __shared__ char smraw[];
    __half* S = (__half*)smraw;
    __half *Qh = S,          *Ql = S + 4608,
           *K0 = S + 9216,   *K1 = S + 18432,
           *V0 = S + 27648,  *V1 = S + 36352,
           *Pt = S + 45056;
    __shared__ float s_msk[128];
    __shared__ float s_rs[64][4];
    __shared__ float s_inv[64];

    const int bh = blockIdx.y, q0 = blockIdx.x * 64, b = bh >> 4;
    const int tid = threadIdx.x, w = tid >> 5, lane = tid & 31;
    const int wq = w >> 2, wn = w & 3;
    const int r = lane >> 2, cq = lane & 3;

    // persistent Q tile [64][64] hi/lo + prefetch pass-1 K stage 0
    #pragma unroll
    for (int i = tid; i < 1024; i += 256) {
        int t = i >> 9, e = i & 511, rr = e >> 3, c8 = e & 7;
        const __half* src = (t ? g_Ql16 : g_Qh16) + ((size_t)bh * LL + q0) * 64;
        cp16((t ? Ql : Qh) + rr * SQ + c8 * 8, src + (size_t)rr * 64 + c8 * 8);
    }
    #pragma unroll
    for (int i = tid; i < 1024; i += 256) {
        int rr = i >> 3, c8 = i & 7;
        cp16(K0 + rr * SQ + c8 * 8,
             g_K16 + (size_t)bh * LL * 64 + (size_t)rr * 64 + c8 * 8);
    }
    CP_COMMIT();

    float rs[2][2] = {{0,0},{0,0}};

    // ---------------- pass 1: rowsums (Qh.K, double-buffered) --------------
    for (int kt = 0; kt < 16; kt++) {
        __syncthreads();
        const __half* Kcur = (kt & 1) ? K1 : K0;
        if (kt + 1 < 16) {
            __half* Knxt = (kt & 1) ? K0 : K1;
            const __half* src = g_K16 + ((size_t)bh * LL + (kt + 1) * 128) * 64;
            #pragma unroll
            for (int i = tid; i < 1024; i += 256) {
                int rr = i >> 3, c8 = i & 7;
                cp16(Knxt + rr * SQ + c8 * 8, src + (size_t)rr * 64 + c8 * 8);
            }
            CP_COMMIT();
            asm volatile("cp.async.wait_group 1;" ::: "memory");
        } else {
            asm volatile("cp.async.wait_group 0;" ::: "memory");
        }
        if (tid < 128) s_msk[tid] = mask[b * LL + kt * 128 + tid] ? 1.f : 0.f;
        __syncthreads();

        float Cs[2][4][4];
        #pragma unroll
        for (int i=0;i<2;i++) for (int j=0;j<4;j++) for (int q=0;q<4;q++) Cs[i][j][q]=0.f;
        #pragma unroll
        for (int ks = 0; ks < 4; ks++) {
            uint32_t fbh[4][2];
            #pragma unroll
            for (int nt = 0; nt < 4; nt++)
                ldmB(fbh[nt], Kcur, SQ, wn * 32 + nt * 8, ks * 16, lane);
            #pragma unroll
            for (int mt = 0; mt < 2; mt++) {
                uint32_t fah[4];
                ldmA(fah, Qh, SQ, wq * 32 + mt * 16, ks * 16, lane);
                #pragma unroll
                for (int nt = 0; nt < 4; nt++)
                    mma16816(Cs[mt][nt], fah, fbh[nt]);
            }
        }
        #pragma unroll
        for (int mt = 0; mt < 2; mt++)
            #pragma unroll
            for (int nt = 0; nt < 4; nt++) {
                int col = wn * 32 + nt * 8 + 2 * cq;
                float m0 = s_msk[col], m1 = s_msk[col + 1];
                #pragma unroll
                for (int hf = 0; hf < 2; hf++)
                    rs[mt][hf] += fex2(Cs[mt][nt][hf*2+0]) * m0
                                + fex2(Cs[mt][nt][hf*2+1]) * m1;
            }
    }

    #pragma unroll
    for (int mt = 0; mt < 2; mt++)
        #pragma unroll
        for (int hf = 0; hf < 2; hf++) {
            rs[mt][hf] += __shfl_xor_sync(0xffffffffu, rs[mt][hf], 1);
            rs[mt][hf] += __shfl_xor_sync(0xffffffffu, rs[mt][hf], 2);
        }
    __syncthreads();
    if (cq == 0) {
        #pragma unroll
        for (int mt = 0; mt < 2; mt++)
            #pragma unroll
            for (int hf = 0; hf < 2; hf++)
                s_rs[wq * 32 + mt * 16 + r + hf * 8][wn] = rs[mt][hf];
    }
    __syncthreads();
    if (tid < 64)
        s_inv[tid] = 1.f / (s_rs[tid][0] + s_rs[tid][1] + s_rs[tid][2] + s_rs[tid][3]);
    __syncthreads();

    float O[2][2][4];
    #pragma unroll
    for (int i=0;i<2;i++) for (int j=0;j<2;j++) for (int q=0;q<4;q++) O[i][j][q]=0.f;
    float inv_r[2][2];
    #pragma unroll
    for (int mt = 0; mt < 2; mt++)
        #pragma unroll
        for (int hf = 0; hf < 2; hf++)
            inv_r[mt][hf] = s_inv[wq * 32 + mt * 16 + r + hf * 8];

    // prologue pass 2: load kt=0 K,V into buffer 0
    {
        const __half* srcK = g_K16 + (size_t)bh * LL * 64;
        const __half* srcV = g_V16 + (size_t)bh * 64 * LL;
        #pragma unroll
        for (int i = tid; i < 1024; i += 256) {
            int rr = i >> 3, c8 = i & 7;
            cp16(K0 + rr * SQ + c8 * 8, srcK + (size_t)rr * 64 + c8 * 8);
        }
        #pragma unroll
        for (int i = tid; i < 1024; i += 256) {
            int rr = i >> 4, c8 = i & 15;
            cp16(V0 + rr * SV + c8 * 8, srcV + (size_t)rr * LL + c8 * 8);
        }
        CP_COMMIT();
    }

    // ---------------- pass 2: normalized attn + O (K/V double-buffered) ----
    for (int kt = 0; kt < 16; kt++) {
        const int k0g = kt * 128;
        const __half *Kc = (kt & 1) ? K1 : K0;
        const __half *Vc = (kt & 1) ? V1 : V0;
        __syncthreads();                       // PV(kt-1) done everywhere
        if (kt + 1 < 16) {
            __half* Kn = (kt & 1) ? K0 : K1;
            __half* Vn = (kt & 1) ? V0 : V1;
            const __half* srcK = g_K16 + ((size_t)bh * LL + k0g + 128) * 64;
            const __half* srcV = g_V16 + (size_t)bh * 64 * LL + k0g + 128;
            #pragma unroll
            for (int i = tid; i < 1024; i += 256) {
                int rr = i >> 3, c8 = i & 7;
                cp16(Kn + rr * SQ + c8 * 8, srcK + (size_t)rr * 64 + c8 * 8);
            }
            #pragma unroll
            for (int i = tid; i < 1024; i += 256) {
                int rr = i >> 4, c8 = i & 15;
                cp16(Vn + rr * SV + c8 * 8, srcV + (size_t)rr * LL + c8 * 8);
            }
            CP_COMMIT();
            asm volatile("cp.async.wait_group 1;" ::: "memory");
        } else {
            asm volatile("cp.async.wait_group 0;" ::: "memory");
        }
        if (tid < 128) s_msk[tid] = mask[b * LL + k0g + tid] ? 1.f : 0.f;
        __syncthreads();

        float Cs[2][4][4];
        #pragma unroll
        for (int i=0;i<2;i++) for (int j=0;j<4;j++) for (int q=0;q<4;q++) Cs[i][j][q]=0.f;
        #pragma unroll
        for (int ks = 0; ks < 4; ks++) {
            uint32_t fbh[4][2];
            #pragma unroll
            for (int nt = 0; nt < 4; nt++)
                ldmB(fbh[nt], Kc, SQ, wn * 32 + nt * 8, ks * 16, lane);
            #pragma unroll
            for (int mt = 0; mt < 2; mt++) {
                uint32_t fah[4], fal[4];
                ldmA(fah, Qh, SQ, wq * 32 + mt * 16, ks * 16, lane);
                ldmA(fal, Ql, SQ, wq * 32 + mt * 16, ks * 16, lane);
                #pragma unroll
                for (int nt = 0; nt < 4; nt++) {
                    mma16816(Cs[mt][nt], fah, fbh[nt]);
                    mma16816(Cs[mt][nt], fal, fbh[nt]);
                }
            }
        }

        #pragma unroll
        for (int mt = 0; mt < 2; mt++) {
            #pragma unroll
            for (int nt = 0; nt < 4; nt++) {
                int col = wn * 32 + nt * 8 + 2 * cq;
                float m0 = s_msk[col], m1 = s_msk[col + 1];
                #pragma unroll
                for (int hf = 0; hf < 2; hf++) {
                    int row = wq * 32 + mt * 16 + r + hf * 8;
                    float iv = inv_r[mt][hf];
                    float e0 = fex2(Cs[mt][nt][hf*2+0]) * m0 * iv;
                    float e1 = fex2(Cs[mt][nt][hf*2+1]) * m1 * iv;
                    if (attn)
                        *(float2*)(attn + ((size_t)bh * LL + q0 + row) * LL + k0g + col) =
                            make_float2(e0, e1);
                    *(__half2*)(Pt + (size_t)row * SV + col) =
                        __halves2half2(__float2half_rn(e0), __float2half_rn(e1));
                }
            }
        }
        __syncthreads();

        #pragma unroll
        for (int ks = 0; ks < 8; ks++) {
            uint32_t vbh[2][2];
            #pragma unroll
            for (int nt = 0; nt < 2; nt++)
                ldmB(vbh[nt], Vc, SV, wn * 16 + nt * 8, ks * 16, lane);
            #pragma unroll
            for (int mt = 0; mt < 2; mt++) {
                uint32_t pah[4];
                ldmA(pah, Pt, SV, wq * 32 + mt * 16, ks * 16, lane);
                #pragma unroll
                for (int nt = 0; nt < 2; nt++)
                    mma16816(O[mt][nt], pah, vbh[nt]);
            }
        }
    }

    // ---- O epilogue (already normalized; hi only) ----
    #pragma unroll
    for (int mt = 0; mt < 2; mt++) {
        #pragma unroll
        for (int nt = 0; nt < 2; nt++) {
            int d = wn * 16 + nt * 8 + 2 * cq;
            #pragma unroll
            for (int hf = 0; hf < 2; hf++) {
                int row = wq * 32 + mt * 16 + r + hf * 8;
                size_t idx = ((size_t)b * LL + q0 + row) * DM + (bh & 15) * 64 + d;
                *(__half2*)(g_O16 + idx) =
                    __halves2half2(__float2half_rn(O[mt][nt][hf*2+0]),
                                   __float2half_rn(O[mt][nt][hf*2+1]));
            }
        }
    }
}

// ============================================================================
extern "C" void kernel_launch(void* const* d_in, const int* in_sizes, int n_in,
                              void* d_out, int out_size)
{
    const float* x    = (const float*)d_in[0];
    const int*   mask = (const int*)  d_in[1];
    const float* bq   = (const float*)d_in[3];
    const float* bk   = (const float*)d_in[5];
    const float* bv   = (const float*)d_in[7];
    const float* bo   = (const float*)d_in[9];
    float* out = (float*)d_out;

    const size_t out_elems  = (size_t)MM * DM;
    const size_t attn_elems = (size_t)BB * NH * LL * LL;
    float* attn = ((size_t)out_size >= out_elems + attn_elems) ? (out + out_elems) : nullptr;

    const int smem_proj = 2 * STG * 2;     // 73728 B
    const int smem_attn = 107520;
    cudaFuncSetAttribute(proj_kernel, cudaFuncAttributeMaxDynamicSharedMemorySize, smem_proj);
    cudaFuncSetAttribute(attn_kernel, cudaFuncAttributeMaxDynamicSharedMemorySize, smem_attn);

    const size_t total_cvt = (size_t)MM * DM + 4 * (size_t)DM * DM;
    cvt_all_kernel<<<(int)(total_cvt / 8 / 256), 256>>>(
        x, (const float*)d_in[2], (const float*)d_in[4],
        (const float*)d_in[6], (const float*)d_in[8]);

    proj_kernel<<<dim3(8, 32, 3), 256, smem_proj>>>(bq, bk, bv, nullptr, -1);

    attn_kernel<<<dim3(LL / 64, BB * NH), 256, smem_attn>>>(mask, attn);

    proj_kernel<<<dim3(8, 32, 1), 256, smem_proj>>>(bo, nullptr, nullptr, out, 3);
}